// round 12
// baseline (speedup 1.0000x reference)
#include <cuda_runtime.h>
#include <cuda_fp16.h>
#include <cstdint>
#include <cstdio>

#define IN_DIM  2048
#define OUT_DIM 5632
#define M_TOT   8192
#define GROUP   128

// GEMM tiling (fp16 operands, fp32 accumulate)
#define BM 128
#define BN 128
#define BKH 64                       /* k-halves per tile = 128 B/row */
#define NKT (IN_DIM / BKH)           /* 32 */
#define A_ST (BM * 128)              /* 16384 */
#define B_ST (BN * 128)              /* 16384 */
#define ST_BYTES (A_ST + B_ST)       /* 32768 */
#define STAGES 3
#define SMEM_TOTAL (STAGES * ST_BYTES)  /* 98304 -> 2 CTAs/SM */

// Static device scratch (no runtime allocation)
__device__ __align__(16) __half g_Xh[(size_t)M_TOT * IN_DIM];    // X in fp16
__device__ __align__(16) __half g_Wh[(size_t)OUT_DIM * IN_DIM];  // dequant W + LoRA, fp16
__device__ __align__(16) float  g_At[16 * IN_DIM];               // 2.0 * lora_A^T

// ---------------------------------------------------------------------------
// fused: convert X -> fp16 AND build At (blocks 0..127 also do At elements)
// ---------------------------------------------------------------------------
__global__ void conv_x_at_kernel(const float* __restrict__ X,
                                 const float* __restrict__ lora_A) {
    const int b = blockIdx.x;
    if (b < 128) {
        int idx = b * blockDim.x + threadIdx.x;   // over IN_DIM*16 = 32768
        int i = idx >> 4;
        int r = idx & 15;
        g_At[r * IN_DIM + i] = 2.0f * lora_A[idx];
    }
    size_t i = ((size_t)b * blockDim.x + threadIdx.x) * 8;
    if (i >= (size_t)M_TOT * IN_DIM) return;
    float4 v0 = *reinterpret_cast<const float4*>(X + i);
    float4 v1 = *reinterpret_cast<const float4*>(X + i + 4);
    __half2 h0 = __floats2half2_rn(v0.x, v0.y);
    __half2 h1 = __floats2half2_rn(v0.z, v0.w);
    __half2 h2 = __floats2half2_rn(v1.x, v1.y);
    __half2 h3 = __floats2half2_rn(v1.z, v1.w);
    uint4 u;
    u.x = *reinterpret_cast<uint32_t*>(&h0);
    u.y = *reinterpret_cast<uint32_t*>(&h1);
    u.z = *reinterpret_cast<uint32_t*>(&h2);
    u.w = *reinterpret_cast<uint32_t*>(&h3);
    *reinterpret_cast<uint4*>(g_Xh + i) = u;
}

// ---------------------------------------------------------------------------
// dequant int4 + fold LoRA into Wh (fp16):
//   Wh[o][i] = fp16( (q-z)*s + sum_r At[r][i]*B[r][o] )
// ---------------------------------------------------------------------------
__global__ void dequant_fold_kernel(const int*   __restrict__ packed,
                                    const float* __restrict__ scales,
                                    const float* __restrict__ zeros,
                                    const float* __restrict__ lora_B) {
    const int ib = threadIdx.x;          // 0..255 -> i0 = 8*ib
    const int oq = blockIdx.x;           // 0..1407
    const int i0 = ib * 8;

    float acc[4][8];
#pragma unroll
    for (int j = 0; j < 4; j++)
#pragma unroll
        for (int k = 0; k < 8; k++) acc[j][k] = 0.0f;

#pragma unroll
    for (int r = 0; r < 16; r++) {
        const float4 a0 = *reinterpret_cast<const float4*>(&g_At[r * IN_DIM + i0]);
        const float4 a1 = *reinterpret_cast<const float4*>(&g_At[r * IN_DIM + i0 + 4]);
#pragma unroll
        for (int j = 0; j < 4; j++) {
            const int o = oq + j * (OUT_DIM / 4);
            const float bv = lora_B[r * OUT_DIM + o];
            acc[j][0] += a0.x * bv;  acc[j][1] += a0.y * bv;
            acc[j][2] += a0.z * bv;  acc[j][3] += a0.w * bv;
            acc[j][4] += a1.x * bv;  acc[j][5] += a1.y * bv;
            acc[j][6] += a1.z * bv;  acc[j][7] += a1.w * bv;
        }
    }

#pragma unroll
    for (int j = 0; j < 4; j++) {
        const int o = oq + j * (OUT_DIM / 4);
        const int4 pk = *reinterpret_cast<const int4*>(&packed[(size_t)o * (IN_DIM / 2) + ib * 4]);
        const int g = o * (IN_DIM / GROUP) + (ib >> 4);
        const float s = scales[g];
        const float z = zeros[g];

        int v;
        v = pk.x; acc[j][0] += ((v & 15) - z) * s;  acc[j][1] += (((v >> 4) & 15) - z) * s;
        v = pk.y; acc[j][2] += ((v & 15) - z) * s;  acc[j][3] += (((v >> 4) & 15) - z) * s;
        v = pk.z; acc[j][4] += ((v & 15) - z) * s;  acc[j][5] += (((v >> 4) & 15) - z) * s;
        v = pk.w; acc[j][6] += ((v & 15) - z) * s;  acc[j][7] += (((v >> 4) & 15) - z) * s;

        __half2 h0 = __floats2half2_rn(acc[j][0], acc[j][1]);
        __half2 h1 = __floats2half2_rn(acc[j][2], acc[j][3]);
        __half2 h2 = __floats2half2_rn(acc[j][4], acc[j][5]);
        __half2 h3 = __floats2half2_rn(acc[j][6], acc[j][7]);
        uint4 u;
        u.x = *reinterpret_cast<uint32_t*>(&h0);
        u.y = *reinterpret_cast<uint32_t*>(&h1);
        u.z = *reinterpret_cast<uint32_t*>(&h2);
        u.w = *reinterpret_cast<uint32_t*>(&h3);
        *reinterpret_cast<uint4*>(&g_Wh[(size_t)o * IN_DIM + i0]) = u;
    }
}

// ---------------------------------------------------------------------------
// GEMM: C[8192][5632] = Xh * Wh^T  (fp16 mma.sync m16n8k16, fp32 accum)
// CTA tile 128x128x64h, 256 threads (8 warps = 2x4), warp tile 64x32.
// 3-stage cp.async ring, SW128 xor swizzle, 2 CTAs/SM.
// Inner loop: fragment double-buffer — ldsm(ks+1) issued before mma(ks).
// ---------------------------------------------------------------------------
__device__ __forceinline__ void ldsm4(uint32_t& r0, uint32_t& r1, uint32_t& r2, uint32_t& r3,
                                      uint32_t addr) {
    asm volatile("ldmatrix.sync.aligned.m8n8.x4.shared.b16 {%0,%1,%2,%3}, [%4];"
                 : "=r"(r0), "=r"(r1), "=r"(r2), "=r"(r3) : "r"(addr));
}

__device__ __forceinline__ void mma_f16(float* d, const uint32_t* a, const uint32_t* b) {
    asm volatile(
        "mma.sync.aligned.m16n8k16.row.col.f32.f16.f16.f32 "
        "{%0,%1,%2,%3}, {%4,%5,%6,%7}, {%8,%9}, {%0,%1,%2,%3};"
        : "+f"(d[0]), "+f"(d[1]), "+f"(d[2]), "+f"(d[3])
        : "r"(a[0]), "r"(a[1]), "r"(a[2]), "r"(a[3]), "r"(b[0]), "r"(b[1]));
}

extern __shared__ char smem_g[];

__global__ __launch_bounds__(256, 2) void gemm_kernel(float* __restrict__ C) {
    const int tid   = threadIdx.x;
    const int lane  = tid & 31;
    const int warp  = tid >> 5;
    const int warpM = warp >> 2;     // 0..1  (64-row slabs)
    const int warpN = warp & 3;      // 0..3  (32-col slabs)
    const int n0 = blockIdx.x * BN;
    const int m0 = blockIdx.y * BM;

    const uint32_t sb = (uint32_t)__cvta_generic_to_shared(smem_g);

    // ---- strength-reduced load plan
    const int r0c  = tid >> 3;            // base row 0..31
    const int colc = tid & 7;
    const int sw   = (colc ^ (r0c & 7)) << 4;
    const __half* pA = g_Xh + (size_t)(m0 + r0c) * IN_DIM + colc * 8;
    const __half* pB = g_Wh + (size_t)(n0 + r0c) * IN_DIM + colc * 8;
    const uint32_t dA0 = (uint32_t)(r0c * 128 + sw);            // += 4096 per i
    const uint32_t dB0 = (uint32_t)(A_ST + r0c * 128 + sw);

    // ---- ldmatrix per-lane constants
    const int mtx = lane >> 3;
    const int x7  = lane & 7;
    const uint32_t aRowB = (uint32_t)(warpM * 64 + ((mtx & 1) << 3) + x7) * 128;
    const int kcA  = mtx >> 1;
    const uint32_t bRowB = (uint32_t)(warpN * 32 + ((mtx >> 1) << 3) + x7) * 128;
    const int kcB  = mtx & 1;

    float acc[4][4][4];
#pragma unroll
    for (int mi = 0; mi < 4; mi++)
#pragma unroll
        for (int ni = 0; ni < 4; ni++)
#pragma unroll
            for (int e = 0; e < 4; e++) acc[mi][ni][e] = 0.0f;

    // prologue: fill stages 0..1
#pragma unroll
    for (int j = 0; j < STAGES - 1; j++) {
        const uint32_t st = sb + j * ST_BYTES;
#pragma unroll
        for (int i = 0; i < 4; i++) {
            asm volatile("cp.async.cg.shared.global [%0], [%1], 16;"
                         :: "r"(st + dA0 + i * 4096), "l"(pA + (size_t)i * 32 * IN_DIM + j * BKH));
            asm volatile("cp.async.cg.shared.global [%0], [%1], 16;"
                         :: "r"(st + dB0 + i * 4096), "l"(pB + (size_t)i * 32 * IN_DIM + j * BKH));
        }
        asm volatile("cp.async.commit_group;");
    }

    uint32_t a0[4][4], a1[4][4], b0[4][2], b1[4][2];

    for (int kt = 0; kt < NKT; kt++) {
        asm volatile("cp.async.wait_group 1;");
        __syncthreads();   // stage kt visible; slot (kt+2)%3 free (kt-1 compute done)

        const uint32_t stA = sb + (kt % STAGES) * ST_BYTES;
        const uint32_t stB = stA + (uint32_t)A_ST;

        // --- critical path first: ldsm for ks=0 into buffer 0
        {
            const uint32_t tA = stA + ((uint32_t)((0 + kcA) ^ x7) << 4);
#pragma unroll
            for (int mi = 0; mi < 4; mi++)
                ldsm4(a0[mi][0], a0[mi][1], a0[mi][2], a0[mi][3],
                      tA + aRowB + mi * 2048);
            const uint32_t tB = stB + ((uint32_t)((0 + kcB) ^ x7) << 4);
#pragma unroll
            for (int nb = 0; nb < 2; nb++) {
                uint32_t q0, q1, q2, q3;
                ldsm4(q0, q1, q2, q3, tB + bRowB + nb * 2048);
                b0[nb * 2][0] = q0;      b0[nb * 2][1] = q1;
                b0[nb * 2 + 1][0] = q2;  b0[nb * 2 + 1][1] = q3;
            }
        }

        // --- then issue the async prefetch for stage kt+2 (off critical path)
        {
            const int j = kt + STAGES - 1;
            if (j < NKT) {
                const uint32_t st = sb + (j % STAGES) * ST_BYTES;
#pragma unroll
                for (int i = 0; i < 4; i++) {
                    asm volatile("cp.async.cg.shared.global [%0], [%1], 16;"
                                 :: "r"(st + dA0 + i * 4096), "l"(pA + (size_t)i * 32 * IN_DIM + j * BKH));
                    asm volatile("cp.async.cg.shared.global [%0], [%1], 16;"
                                 :: "r"(st + dB0 + i * 4096), "l"(pB + (size_t)i * 32 * IN_DIM + j * BKH));
                }
            }
            asm volatile("cp.async.commit_group;");   // empty at tail keeps counts uniform
        }

        // --- pipelined ks loop: load ks+1 frags, then mma ks
#pragma unroll
        for (int ks = 0; ks < 4; ks++) {
            uint32_t (*ac)[4] = (ks & 1) ? a1 : a0;
            uint32_t (*an)[4] = (ks & 1) ? a0 : a1;
            uint32_t (*bc)[2] = (ks & 1) ? b1 : b0;
            uint32_t (*bn)[2] = (ks & 1) ? b0 : b1;

            if (ks < 3) {
                const uint32_t tA = stA + ((uint32_t)(((ks + 1) * 2 + kcA) ^ x7) << 4);
#pragma unroll
                for (int mi = 0; mi < 4; mi++)
                    ldsm4(an[mi][0], an[mi][1], an[mi][2], an[mi][3],
                          tA + aRowB + mi * 2048);
                const uint32_t tB = stB + ((uint32_t)(((ks + 1) * 2 + kcB) ^ x7) << 4);
#pragma unroll
                for (int nb = 0; nb < 2; nb++) {
                    uint32_t q0, q1, q2, q3;
                    ldsm4(q0, q1, q2, q3, tB + bRowB + nb * 2048);
                    bn[nb * 2][0] = q0;      bn[nb * 2][1] = q1;
                    bn[nb * 2 + 1][0] = q2;  bn[nb * 2 + 1][1] = q3;
                }
            }
#pragma unroll
            for (int mi = 0; mi < 4; mi++)
#pragma unroll
                for (int ni = 0; ni < 4; ni++)
                    mma_f16(acc[mi][ni], ac[mi], bc[ni]);
        }
    }

    // epilogue: direct float2 stores
    const int g  = lane >> 2;
    const int t4 = lane & 3;
#pragma unroll
    for (int mi = 0; mi < 4; mi++) {
        const int row = m0 + warpM * 64 + mi * 16 + g;
#pragma unroll
        for (int ni = 0; ni < 4; ni++) {
            const int col = n0 + warpN * 32 + ni * 8 + t4 * 2;
            *reinterpret_cast<float2*>(&C[(size_t)row * OUT_DIM + col]) =
                make_float2(acc[mi][ni][0], acc[mi][ni][1]);
            *reinterpret_cast<float2*>(&C[(size_t)(row + 8) * OUT_DIM + col]) =
                make_float2(acc[mi][ni][2], acc[mi][ni][3]);
        }
    }
}

// ---------------------------------------------------------------------------
extern "C" void kernel_launch(void* const* d_in, const int* in_sizes, int n_in,
                              void* d_out, int out_size) {
    const float* x      = (const float*)d_in[0];
    const int*   packed = (const int*)  d_in[1];
    const float* scales = (const float*)d_in[2];
    const float* zeros  = (const float*)d_in[3];
    const float* lora_A = (const float*)d_in[4];
    const float* lora_B = (const float*)d_in[5];
    float* out = (float*)d_out;

    conv_x_at_kernel<<<(int)(((size_t)M_TOT * IN_DIM / 8 + 255) / 256), 256>>>(x, lora_A);
    dequant_fold_kernel<<<OUT_DIM / 4, 256>>>(packed, scales, zeros, lora_B);

    cudaFuncSetAttribute(gemm_kernel, cudaFuncAttributeMaxDynamicSharedMemorySize,
                         SMEM_TOTAL);
    dim3 grid(OUT_DIM / BN, M_TOT / BM);
    gemm_kernel<<<grid, 256, SMEM_TOTAL>>>(out);
}